// round 4
// baseline (speedup 1.0000x reference)
#include <cuda_runtime.h>
#include <cuda_bf16.h>

// ConeProjection: out[b,k] = P[k]^T * sigma[b] * P[k]
//   sigma[a][c] = (vn·w_a)(vn·w_c) - alpha*(w_a·w_c)
//   w0 = R[:,0], w1 = R[:,1], w2 = t - eyes, vn = v/max(||v||,1e-14)
//   P[k] = ((k/13 - 6)/6, (k%13 - 6)/6, 1)
//
// Store-bandwidth bound: 88.6 MB out + 10 MB in. Strategy: 16 batches/block,
// sigma coefficients in smem, fully-coalesced float4 output stores.

#define K_GRID   169
#define GROUP    16
#define THREADS  256
#define ELEMS    (GROUP * K_GRID)   // 2704
#define NVEC     (ELEMS / 4)        // 676

__global__ __launch_bounds__(THREADS, 8)
void cone_projection_kernel(const float* __restrict__ eyes,
                            const float* __restrict__ v,
                            const float* __restrict__ R,
                            const float* __restrict__ t,
                            const float* __restrict__ alpha,
                            float* __restrict__ out)
{
    __shared__ float sc[GROUP][6];

    const int tid = threadIdx.x;
    const long long base_b = (long long)blockIdx.x * GROUP;

    // --- Phase 1: threads 0..15 each build sigma coefficients for one batch ---
    if (tid < GROUP) {
        const long long b = base_b + tid;

        float vx = v[b * 3 + 0];
        float vy = v[b * 3 + 1];
        float vz = v[b * 3 + 2];
        float n  = fmaxf(sqrtf(vx * vx + vy * vy + vz * vz), 1e-14f);
        float inv = 1.0f / n;
        vx *= inv; vy *= inv; vz *= inv;

        const float a = alpha[b];

        const float* Rb = R + b * 9;
        // column 0 and column 1 of row-major 3x3
        const float w0x = Rb[0], w0y = Rb[3], w0z = Rb[6];
        const float w1x = Rb[1], w1y = Rb[4], w1z = Rb[7];
        const float w2x = t[b * 3 + 0] - eyes[b * 3 + 0];
        const float w2y = t[b * 3 + 1] - eyes[b * 3 + 1];
        const float w2z = t[b * 3 + 2] - eyes[b * 3 + 2];

        const float d0 = vx * w0x + vy * w0y + vz * w0z;
        const float d1 = vx * w1x + vy * w1y + vz * w1z;
        const float d2 = vx * w2x + vy * w2y + vz * w2z;

        const float s00 = d0 * d0 - a * (w0x * w0x + w0y * w0y + w0z * w0z);
        const float s11 = d1 * d1 - a * (w1x * w1x + w1y * w1y + w1z * w1z);
        const float s22 = d2 * d2 - a * (w2x * w2x + w2y * w2y + w2z * w2z);
        const float s01 = d0 * d1 - a * (w0x * w1x + w0y * w1y + w0z * w1z);
        const float s02 = d0 * d2 - a * (w0x * w2x + w0y * w2y + w0z * w2z);
        const float s12 = d1 * d2 - a * (w1x * w2x + w1y * w2y + w1z * w2z);

        sc[tid][0] = s00;
        sc[tid][1] = s11;
        sc[tid][2] = s22;
        sc[tid][3] = 2.0f * s01;   // xy coefficient
        sc[tid][4] = 2.0f * s02;   // x coefficient
        sc[tid][5] = 2.0f * s12;   // y coefficient
    }
    __syncthreads();

    // --- Phase 2: coalesced float4 output stores ---
    // Block writes ELEMS contiguous floats starting at base_b*169.
    // base_b*169*4 bytes = blockIdx*16*676 B -> 16B aligned, so float4 is legal.
    float4* out4 = reinterpret_cast<float4*>(out + base_b * K_GRID);

    #pragma unroll
    for (int i = tid; i < NVEC; i += THREADS) {
        const int flat = i * 4;
        float r[4];
        #pragma unroll
        for (int e = 0; e < 4; e++) {
            const int f  = flat + e;
            const int bl = f / K_GRID;          // const-divide -> imad/shf
            const int k  = f - bl * K_GRID;
            const int ki = k / 13;
            const int kj = k - ki * 13;
            const float x = (float)(ki - 6) * (1.0f / 6.0f);
            const float y = (float)(kj - 6) * (1.0f / 6.0f);
            const float* c = sc[bl];
            r[e] = c[0] * x * x + c[1] * y * y + c[2]
                 + c[3] * x * y + c[4] * x + c[5] * y;
        }
        out4[i] = make_float4(r[0], r[1], r[2], r[3]);
    }
}

extern "C" void kernel_launch(void* const* d_in, const int* in_sizes, int n_in,
                              void* d_out, int out_size) {
    const float* eyes  = (const float*)d_in[0];
    const float* v     = (const float*)d_in[1];
    const float* R     = (const float*)d_in[2];
    const float* t     = (const float*)d_in[3];
    const float* alpha = (const float*)d_in[4];
    float* out = (float*)d_out;

    const int B = in_sizes[4];          // alpha has B elements
    const int blocks = (B + GROUP - 1) / GROUP;   // 131072/16 = 8192

    cone_projection_kernel<<<blocks, THREADS>>>(eyes, v, R, t, alpha, out);
}

// round 5
// speedup vs baseline: 1.2592x; 1.2592x over previous
#include <cuda_runtime.h>
#include <cuda_bf16.h>

// ConeProjection: out[b,k] = P[k]^T * sigma[b] * P[k]
//   sigma[a][c] = (vn·w_a)(vn·w_c) - alpha*(w_a·w_c)
//   w0 = R[:,0], w1 = R[:,1], w2 = t - eyes, vn = v/max(||v||,1e-14)
//   P[k] = ((ki-6)/6, (kj-6)/6, 1),  k = 13*ki + kj
//
// out[b,k] is a quadratic in (x,y): c0 x^2 + c1 y^2 + c2 + c3 xy + c4 x + c5 y.
// Per (batch,row ki): out = A + B y + C y^2 with
//   A = c2 + c4 x + c0 x^2,  B = c5 + c3 x,  C = c1
// Inner 13-element loop fully unrolled -> 2 FFMA (y immediate) + 1 STS each.
// Block stages 16 batches (2704 floats) in smem, then coalesced float4 copy.

#define K_GRID   169
#define GROUP    16
#define THREADS  256
#define ELEMS    (GROUP * K_GRID)   // 2704
#define NVEC     (ELEMS / 4)        // 676
#define NROWS    (GROUP * 13)       // 208 row-threads

__global__ __launch_bounds__(THREADS, 8)
void cone_projection_kernel(const float* __restrict__ eyes,
                            const float* __restrict__ v,
                            const float* __restrict__ R,
                            const float* __restrict__ t,
                            const float* __restrict__ alpha,
                            float* __restrict__ out,
                            int B)
{
    __shared__ float sc[GROUP][8];            // 6 coeffs + pad (16B-aligned rows)
    __shared__ float sbuf[ELEMS];             // staged block output, global layout

    const int tid = threadIdx.x;
    const long long base_b = (long long)blockIdx.x * GROUP;

    // --- Phase 1: threads 0..15 build the 6 sigma coefficients per batch ---
    if (tid < GROUP && base_b + tid < B) {
        const long long b = base_b + tid;

        float vx = v[b * 3 + 0];
        float vy = v[b * 3 + 1];
        float vz = v[b * 3 + 2];
        float n  = fmaxf(sqrtf(vx * vx + vy * vy + vz * vz), 1e-14f);
        float inv = 1.0f / n;
        vx *= inv; vy *= inv; vz *= inv;

        const float a = alpha[b];

        const float* Rb = R + b * 9;
        const float w0x = Rb[0], w0y = Rb[3], w0z = Rb[6];   // R[:,0]
        const float w1x = Rb[1], w1y = Rb[4], w1z = Rb[7];   // R[:,1]
        const float w2x = t[b * 3 + 0] - eyes[b * 3 + 0];
        const float w2y = t[b * 3 + 1] - eyes[b * 3 + 1];
        const float w2z = t[b * 3 + 2] - eyes[b * 3 + 2];

        const float d0 = vx * w0x + vy * w0y + vz * w0z;
        const float d1 = vx * w1x + vy * w1y + vz * w1z;
        const float d2 = vx * w2x + vy * w2y + vz * w2z;

        const float s00 = d0 * d0 - a * (w0x * w0x + w0y * w0y + w0z * w0z);
        const float s11 = d1 * d1 - a * (w1x * w1x + w1y * w1y + w1z * w1z);
        const float s22 = d2 * d2 - a * (w2x * w2x + w2y * w2y + w2z * w2z);
        const float s01 = d0 * d1 - a * (w0x * w1x + w0y * w1y + w0z * w1z);
        const float s02 = d0 * d2 - a * (w0x * w2x + w0y * w2y + w0z * w2z);
        const float s12 = d1 * d2 - a * (w1x * w2x + w1y * w2y + w1z * w2z);

        sc[tid][0] = s00;          // x^2
        sc[tid][1] = s11;          // y^2
        sc[tid][2] = s22;          // const
        sc[tid][3] = 2.0f * s01;   // xy
        sc[tid][4] = 2.0f * s02;   // x
        sc[tid][5] = 2.0f * s12;   // y
        sc[tid][6] = 0.0f;
        sc[tid][7] = 0.0f;
    }
    __syncthreads();

    // --- Phase 2a: one thread per (batch, ki) row; 13 elems @ 2 FFMA + STS ---
    if (tid < NROWS) {
        const int bl = tid & 15;       // batch within group
        const int ki = tid >> 4;       // grid row 0..12
        if (base_b + bl < B) {
            const float4 cA = *reinterpret_cast<const float4*>(&sc[bl][0]); // c0,c1,c2,c3
            const float4 cB = *reinterpret_cast<const float4*>(&sc[bl][4]); // c4,c5,0,0

            const float x = (float)(ki - 6) * (1.0f / 6.0f);
            const float A  = fmaf(fmaf(cA.x, x, cB.x), x, cA.z); // c2 + c4 x + c0 x^2
            const float Bq = fmaf(cA.w, x, cB.y);                // c5 + c3 x
            const float C  = cA.y;                               // c1

            float* row = &sbuf[bl * K_GRID + ki * 13];
            #pragma unroll
            for (int kj = 0; kj < 13; ++kj) {
                const float y = (float)(kj - 6) * (1.0f / 6.0f); // literal constant
                row[kj] = fmaf(fmaf(C, y, Bq), y, A);
            }
        }
    }
    __syncthreads();

    // --- Phase 2b: coalesced float4 copy, smem -> gmem (layouts identical) ---
    const long long rem = (long long)B - base_b;
    if (rem >= GROUP) {
        float4* out4 = reinterpret_cast<float4*>(out + base_b * K_GRID);
        const float4* s4 = reinterpret_cast<const float4*>(sbuf);
        #pragma unroll
        for (int i = tid; i < NVEC; i += THREADS)
            out4[i] = s4[i];
    } else {
        // tail block (B not multiple of 16): scalar copy of valid batches
        const int nval = (int)rem * K_GRID;
        for (int i = tid; i < nval; i += THREADS)
            out[base_b * K_GRID + i] = sbuf[i];
    }
}

extern "C" void kernel_launch(void* const* d_in, const int* in_sizes, int n_in,
                              void* d_out, int out_size) {
    const float* eyes  = (const float*)d_in[0];
    const float* v     = (const float*)d_in[1];
    const float* R     = (const float*)d_in[2];
    const float* t     = (const float*)d_in[3];
    const float* alpha = (const float*)d_in[4];
    float* out = (float*)d_out;

    const int B = in_sizes[4];                    // alpha: B elements
    const int blocks = (B + GROUP - 1) / GROUP;   // 8192 for B=131072

    cone_projection_kernel<<<blocks, THREADS>>>(eyes, v, R, t, alpha, out, B);
}